// round 1
// baseline (speedup 1.0000x reference)
#include <cuda_runtime.h>

// Problem constants (fixed by the reference: x=(128,128,16,16) f32, logits=(128,100))
#define B_  128
#define D_  32768          // C*H*W
#define D4_ (D_/4)         // 8192 float4 per prototype row
#define K_  100
#define TILE_ 10           // 10x10 class tile in the broadcast kernel

// Scratch (allocation-free rule: __device__ globals)
__device__ int   g_cls[B_];
__device__ int   g_items[B_];    // CSR items: batch indices grouped by class, ascending
__device__ int   g_off[K_ + 1];  // CSR offsets
__device__ float g_inv[K_];      // 1/count (0 if count==0)

// ---------------------------------------------------------------------------
// Kernel 1: argmax per batch row + deterministic CSR build (single block).
// softmax is monotone -> argmax(probs) == argmax(logits). First-max semantics
// (strict >) matches jnp.argmax tie-breaking.
// ---------------------------------------------------------------------------
__global__ void argmax_csr_kernel(const float* __restrict__ logits) {
    int b = threadIdx.x;
    if (b < B_) {
        const float* row = logits + (size_t)b * K_;
        float best = row[0];
        int   arg  = 0;
        #pragma unroll 4
        for (int k = 1; k < K_; k++) {
            float v = row[k];
            if (v > best) { best = v; arg = k; }
        }
        g_cls[b] = arg;
    }
    __syncthreads();
    // Serial CSR build on thread 0: fixed order -> bitwise-deterministic sums.
    if (threadIdx.x == 0) {
        int cnt[K_];
        #pragma unroll 4
        for (int k = 0; k < K_; k++) cnt[k] = 0;
        for (int bb = 0; bb < B_; bb++) cnt[g_cls[bb]]++;
        int off = 0;
        int pos[K_];
        for (int k = 0; k < K_; k++) {
            g_off[k] = off;
            pos[k]   = off;
            g_inv[k] = (cnt[k] > 0) ? (1.0f / (float)cnt[k]) : 0.0f;
            off += cnt[k];
        }
        g_off[K_] = off;
        for (int bb = 0; bb < B_; bb++) {
            int c = g_cls[bb];
            g_items[pos[c]++] = bb;   // ascending b within each class
        }
    }
}

// ---------------------------------------------------------------------------
// Kernel 2: prototypes[k][d] = mean over assigned batches (via CSR).
// grid = (D4/256, K). Reads x exactly once (coalesced float4), deterministic
// fixed-order accumulation, writes 12.8 MB.
// ---------------------------------------------------------------------------
__global__ void proto_kernel(const float4* __restrict__ x4,
                             float4* __restrict__ proto4) {
    int d4 = blockIdx.x * blockDim.x + threadIdx.x;   // 0..D4-1
    int k  = blockIdx.y;

    float4 acc = make_float4(0.f, 0.f, 0.f, 0.f);
    int s = g_off[k];
    int e = g_off[k + 1];
    for (int t = s; t < e; t++) {
        int b = g_items[t];
        float4 v = x4[(size_t)b * D4_ + d4];
        acc.x += v.x; acc.y += v.y; acc.z += v.z; acc.w += v.w;
    }
    float inv = g_inv[k];  // count==0 -> acc==0 and inv==0 -> 0 (matches where())
    acc.x *= inv; acc.y *= inv; acc.z *= inv; acc.w *= inv;
    proto4[(size_t)k * D4_ + d4] = acc;
}

// ---------------------------------------------------------------------------
// Kernel 3: inter[i][j][d] = proto[j][d] - proto[i][d].
// 1.31 GB of writes -> DRAM-write bound. 10x10 class tile per block:
// pj[10] held in registers, pi streamed -> L2 read traffic is only 0.2x of
// the write stream. All stores are coalesced STG.128.
// grid = (D4/256, 100 tiles), block = 256.
// ---------------------------------------------------------------------------
__global__ __launch_bounds__(256) void inter_kernel(
        const float4* __restrict__ proto4,
        float4* __restrict__ out4) {
    int d4   = blockIdx.x * 256 + threadIdx.x;     // 0..D4-1
    int tile = blockIdx.y;                         // 0..99
    int i0 = (tile / TILE_) * TILE_;
    int j0 = (tile % TILE_) * TILE_;

    float4 pj[TILE_];
    #pragma unroll
    for (int jj = 0; jj < TILE_; jj++)
        pj[jj] = proto4[(size_t)(j0 + jj) * D4_ + d4];

    #pragma unroll
    for (int ii = 0; ii < TILE_; ii++) {
        float4 pi = proto4[(size_t)(i0 + ii) * D4_ + d4];
        #pragma unroll
        for (int jj = 0; jj < TILE_; jj++) {
            float4 r;
            r.x = pj[jj].x - pi.x;
            r.y = pj[jj].y - pi.y;
            r.z = pj[jj].z - pi.z;
            r.w = pj[jj].w - pi.w;
            out4[(size_t)((i0 + ii) * K_ + (j0 + jj)) * D4_ + d4] = r;
        }
    }
}

// ---------------------------------------------------------------------------
// Launcher. Output layout: [prototypes (100*32768 f32) | inter (100*100*32768 f32)]
// ---------------------------------------------------------------------------
extern "C" void kernel_launch(void* const* d_in, const int* in_sizes, int n_in,
                              void* d_out, int out_size) {
    const float* x      = (const float*)d_in[0];   // (128,128,16,16) f32
    const float* logits = (const float*)d_in[1];   // (128,100) f32
    float* out = (float*)d_out;

    const float4* x4     = (const float4*)x;
    float4*       proto4 = (float4*)out;                       // first 819200 float4
    float4*       inter4 = (float4*)out + (size_t)K_ * D4_;    // rest

    argmax_csr_kernel<<<1, 128>>>(logits);

    dim3 gp(D4_ / 256, K_);        // 32 x 100
    proto_kernel<<<gp, 256>>>(x4, proto4);

    dim3 gi(D4_ / 256, K_);        // 32 x 100 tiles (10x10 class tiles)
    inter_kernel<<<gi, 256>>>(proto4, inter4);
}

// round 2
// speedup vs baseline: 1.0519x; 1.0519x over previous
#include <cuda_runtime.h>

// Problem constants (fixed by the reference: x=(128,128,16,16) f32, logits=(128,100))
#define B_  128
#define D_  32768          // C*H*W
#define D4_ (D_/4)         // 8192 float4 per prototype row
#define K_  100
#define TILE_ 10           // 10x10 class tile in the broadcast kernel

// Scratch (allocation-free rule: __device__ globals)
__device__ int   g_items[B_];    // CSR items: batch indices grouped by class, ascending
__device__ int   g_off[K_ + 1];  // CSR offsets
__device__ float g_inv[K_];      // 1/count (0 if count==0)

// ---------------------------------------------------------------------------
// Kernel 1: argmax per batch row + deterministic CSR build, all in shared mem.
// softmax is monotone -> argmax(probs) == argmax(logits). Strict > matches
// jnp.argmax first-max tie-breaking.
//   - counts: smem atomicAdd (order-independent -> deterministic)
//   - offsets: thread-0 serial prefix over 100 smem ints (no global latency)
//   - placement: thread b computes rank = #{b' < b : cls[b']==cls[b]} by a
//     parallel scan of the 128 smem class ids -> stable, deterministic CSR.
// ---------------------------------------------------------------------------
__global__ void argmax_csr_kernel(const float* __restrict__ logits) {
    __shared__ int   s_cls[B_];
    __shared__ int   s_cnt[K_];
    __shared__ int   s_off[K_ + 1];

    int b = threadIdx.x;   // 0..127, blockDim.x == 128

    // zero counts (first 100 threads)
    if (b < K_) s_cnt[b] = 0;

    // per-row argmax
    const float* row = logits + (size_t)b * K_;
    float best = row[0];
    int   arg  = 0;
    #pragma unroll 4
    for (int k = 1; k < K_; k++) {
        float v = row[k];
        if (v > best) { best = v; arg = k; }
    }
    __syncthreads();          // counts zeroed before atomics
    s_cls[b] = arg;
    atomicAdd(&s_cnt[arg], 1);
    __syncthreads();

    // prefix sum over 100 classes (serial on thread 0, all in smem: ~fast)
    if (b == 0) {
        int off = 0;
        #pragma unroll 4
        for (int k = 0; k < K_; k++) {
            s_off[k] = off;
            off += s_cnt[k];
        }
        s_off[K_] = off;
    }
    __syncthreads();

    // deterministic rank within class: count of earlier rows with same class
    int myc = s_cls[b];
    int rank = 0;
    #pragma unroll 8
    for (int bb = 0; bb < B_; bb++) {
        rank += (bb < b && s_cls[bb] == myc) ? 1 : 0;
    }
    g_items[s_off[myc] + rank] = b;

    // publish offsets + inverse counts
    if (b < K_) {
        g_off[b] = s_off[b];
        int c = s_cnt[b];
        g_inv[b] = (c > 0) ? (1.0f / (float)c) : 0.0f;
    }
    if (b == 0) g_off[K_] = s_off[K_];
}

// ---------------------------------------------------------------------------
// Kernel 2: prototypes[k][d] = mean over assigned batches (via CSR).
// grid = (D4/256, K). Reads x exactly once overall (coalesced float4),
// deterministic fixed-order accumulation, writes 12.8 MB.
// ---------------------------------------------------------------------------
__global__ void proto_kernel(const float4* __restrict__ x4,
                             float4* __restrict__ proto4) {
    int d4 = blockIdx.x * blockDim.x + threadIdx.x;   // 0..D4-1
    int k  = blockIdx.y;

    float4 acc = make_float4(0.f, 0.f, 0.f, 0.f);
    int s = g_off[k];
    int e = g_off[k + 1];
    for (int t = s; t < e; t++) {
        int b = g_items[t];
        float4 v = x4[(size_t)b * D4_ + d4];
        acc.x += v.x; acc.y += v.y; acc.z += v.z; acc.w += v.w;
    }
    float inv = g_inv[k];  // count==0 -> acc==0 and inv==0 -> 0 (matches where())
    acc.x *= inv; acc.y *= inv; acc.z *= inv; acc.w *= inv;
    proto4[(size_t)k * D4_ + d4] = acc;
}

// ---------------------------------------------------------------------------
// Kernel 3: inter[i][j][d] = proto[j][d] - proto[i][d].
// 1.31 GB of writes -> DRAM-write bound. 10x10 class tile per block:
// pj[10] held in registers, pi streamed -> L2 read traffic is only 0.2x of
// the write stream (prototypes resident in L2). All stores coalesced STG.128.
// grid = (D4/256, 100 tiles), block = 256.
// ---------------------------------------------------------------------------
__global__ __launch_bounds__(256) void inter_kernel(
        const float4* __restrict__ proto4,
        float4* __restrict__ out4) {
    int d4   = blockIdx.x * 256 + threadIdx.x;     // 0..D4-1
    int tile = blockIdx.y;                         // 0..99
    int i0 = (tile / TILE_) * TILE_;
    int j0 = (tile % TILE_) * TILE_;

    float4 pj[TILE_];
    #pragma unroll
    for (int jj = 0; jj < TILE_; jj++)
        pj[jj] = proto4[(size_t)(j0 + jj) * D4_ + d4];

    #pragma unroll
    for (int ii = 0; ii < TILE_; ii++) {
        float4 pi = proto4[(size_t)(i0 + ii) * D4_ + d4];
        #pragma unroll
        for (int jj = 0; jj < TILE_; jj++) {
            float4 r;
            r.x = pj[jj].x - pi.x;
            r.y = pj[jj].y - pi.y;
            r.z = pj[jj].z - pi.z;
            r.w = pj[jj].w - pi.w;
            out4[(size_t)((i0 + ii) * K_ + (j0 + jj)) * D4_ + d4] = r;
        }
    }
}

// ---------------------------------------------------------------------------
// Launcher. Output layout: [prototypes (100*32768 f32) | inter (100*100*32768 f32)]
// ---------------------------------------------------------------------------
extern "C" void kernel_launch(void* const* d_in, const int* in_sizes, int n_in,
                              void* d_out, int out_size) {
    const float* x      = (const float*)d_in[0];   // (128,128,16,16) f32
    const float* logits = (const float*)d_in[1];   // (128,100) f32
    float* out = (float*)d_out;

    const float4* x4     = (const float4*)x;
    float4*       proto4 = (float4*)out;                       // first 819200 float4
    float4*       inter4 = (float4*)out + (size_t)K_ * D4_;    // rest

    argmax_csr_kernel<<<1, 128>>>(logits);

    dim3 gp(D4_ / 256, K_);        // 32 x 100
    proto_kernel<<<gp, 256>>>(x4, proto4);

    dim3 gi(D4_ / 256, K_);        // 32 x 100 tiles (10x10 class tiles)
    inter_kernel<<<gi, 256>>>(proto4, inter4);
}